// round 1
// baseline (speedup 1.0000x reference)
#include <cuda_runtime.h>

// TreeLSTMCell fused kernel — round 1 (SIMT fp32, packed f32x2 FMA).
//
// Math (reference):
//   f_pre[n,d,k]  = sum_h nh[n,d,h] * U_f[d,h,k] + b_f[d,k]
//   f             = sigmoid(f_pre + f_input[n,k])
//   c_aggr[n,k]   = sum_d f[n,d,k] * nc[n,d,k]
//   iou_aggr[n,k] = sum_{d,h} nh[n,d,h] * U_aggr[d,h,k] + b_aggr[k]
//   iou = iou_input + iou_aggr ; i,o,u = split(iou)
//   c = sigmoid(i)*tanh(u) + c_aggr ; h = sigmoid(o)*tanh(c)
// Output layout: out[0 : N*H] = h, out[N*H : 2*N*H] = c (flattened, concat order of return).

#define NN      100000
#define DEG     8
#define HH      128
#define TM      64          // nodes per CTA
#define THREADS 512

typedef unsigned long long ull;

__device__ __forceinline__ ull pack2(float a, float b) {
    ull r; asm("mov.b64 %0, {%1,%2};" : "=l"(r) : "f"(a), "f"(b)); return r;
}
__device__ __forceinline__ void unpack2(ull v, float& a, float& b) {
    asm("mov.b64 {%0,%1}, %2;" : "=f"(a), "=f"(b) : "l"(v));
}
// Blackwell packed fp32x2 FMA (2 MACs / instruction; ptxas won't emit from C++)
__device__ __forceinline__ ull ffma2(ull a, ull b, ull c) {
    ull d; asm("fma.rn.f32x2 %0, %1, %2, %3;" : "=l"(d) : "l"(a), "l"(b), "l"(c)); return d;
}
__device__ __forceinline__ float sigmoidf_(float x) {
    return 1.f / (1.f + __expf(-x));
}
__device__ __forceinline__ void unpack8(const ull a[4], float o[8]) {
    unpack2(a[0], o[0], o[1]); unpack2(a[1], o[2], o[3]);
    unpack2(a[2], o[4], o[5]); unpack2(a[3], o[6], o[7]);
}

// 2 nodes x 8 cols register-tile GEMM over K=128 from shared memory.
// shW: [128][128] (k-major rows), h0p/h1p: rows of the h tile, col0: this thread's column base.
__device__ __forceinline__ void gemm_2x8(const float* __restrict__ shW,
                                         const float* __restrict__ h0p,
                                         const float* __restrict__ h1p,
                                         int col0, ull a0[4], ull a1[4]) {
#pragma unroll 8
    for (int k = 0; k < HH; k++) {
        const float* wr = shW + k * HH + col0;
        ulonglong2 wa = *(const ulonglong2*)(wr);        // cols (0,1),(2,3)
        ulonglong2 wb = *(const ulonglong2*)(wr + 4);    // cols (4,5),(6,7)
        float h0 = h0p[k];
        float h1 = h1p[k];
        ull hp0 = pack2(h0, h0);
        ull hp1 = pack2(h1, h1);
        a0[0] = ffma2(hp0, wa.x, a0[0]);
        a0[1] = ffma2(hp0, wa.y, a0[1]);
        a0[2] = ffma2(hp0, wb.x, a0[2]);
        a0[3] = ffma2(hp0, wb.y, a0[3]);
        a1[0] = ffma2(hp1, wa.x, a1[0]);
        a1[1] = ffma2(hp1, wa.y, a1[1]);
        a1[2] = ffma2(hp1, wb.x, a1[2]);
        a1[3] = ffma2(hp1, wb.y, a1[3]);
    }
}

// Shared memory layout (floats):
//   [0      : 16384) W chunk  128x128
//   [16384  : 24576) h tile   64x128
//   [24576  : 32768) f_input  64x128
//   [32768  : 33792) b_f      8x128
//   [33792  : 34176) b_aggr   384
#define SH_W   0
#define SH_H   16384
#define SH_FI  24576
#define SH_BF  32768
#define SH_BA  33792
#define SMEM_FLOATS 34176

__global__ __launch_bounds__(THREADS, 1)
void tree_lstm_kernel(const float* __restrict__ nh, const float* __restrict__ nc,
                      const float* __restrict__ f_in, const float* __restrict__ iou_in,
                      const float* __restrict__ Uf, const float* __restrict__ bf,
                      const float* __restrict__ Ua, const float* __restrict__ ba,
                      float* __restrict__ out) {
    extern __shared__ float sm[];
    float* sh_w  = sm + SH_W;
    float* sh_h  = sm + SH_H;
    float* sh_fi = sm + SH_FI;
    float* sh_bf = sm + SH_BF;
    float* sh_ba = sm + SH_BA;

    const int tid  = threadIdx.x;
    const int nb   = blockIdx.x * TM;
    const int cg   = tid & 15;
    const int col0 = cg * 8;
    const int ng   = tid >> 4;        // 0..31
    const int ln0  = ng * 2, ln1 = ln0 + 1;
    const int n0   = nb + ln0, n1 = nb + ln1;
    const bool v0  = n0 < NN, v1 = n1 < NN;

    // ---- one-time preloads (biases + f_input tile) ----
    for (int i = tid; i < DEG * HH; i += THREADS) sh_bf[i] = bf[i];
    if (tid < 3 * HH) sh_ba[tid] = ba[tid];
#pragma unroll
    for (int i = 0; i < (TM * HH / 4) / THREADS; i++) {
        int idx = tid + i * THREADS;            // float4 index 0..2047
        int row = idx >> 5, c4 = idx & 31;
        int n = nb + row;
        float4 v = make_float4(0.f, 0.f, 0.f, 0.f);
        if (n < NN) v = *(const float4*)(f_in + (size_t)n * HH + c4 * 4);
        ((float4*)sh_fi)[idx] = v;
    }

    // ---- persistent accumulators ----
    ull ai0[4] = {0,0,0,0}, ai1[4] = {0,0,0,0};
    ull ao0[4] = {0,0,0,0}, ao1[4] = {0,0,0,0};
    ull au0[4] = {0,0,0,0}, au1[4] = {0,0,0,0};
    float cag0[8], cag1[8];
#pragma unroll
    for (int j = 0; j < 8; j++) { cag0[j] = 0.f; cag1[j] = 0.f; }

    const float* h0p = sh_h + ln0 * HH;
    const float* h1p = sh_h + ln1 * HH;

    for (int d = 0; d < DEG; d++) {
        __syncthreads();  // previous chunk's compute done before overwriting sh_h/sh_w

        // load h tile for this d  (zero-pad invalid nodes)
#pragma unroll
        for (int i = 0; i < (TM * HH / 4) / THREADS; i++) {
            int idx = tid + i * THREADS;
            int row = idx >> 5, c4 = idx & 31;
            int n = nb + row;
            float4 v = make_float4(0.f, 0.f, 0.f, 0.f);
            if (n < NN) v = *(const float4*)(nh + ((size_t)n * DEG + d) * HH + c4 * 4);
            ((float4*)sh_h)[idx] = v;
        }
        // load W = U_f[d]  (contiguous 128x128)
        {
            const float4* src = (const float4*)(Uf + (size_t)d * HH * HH);
#pragma unroll
            for (int i = 0; i < (HH * HH / 4) / THREADS; i++)
                ((float4*)sh_w)[tid + i * THREADS] = src[tid + i * THREADS];
        }
        __syncthreads();

        // ---- f chunk: f_pre = h_d @ U_f[d] ----
        ull f0a[4] = {0,0,0,0}, f1a[4] = {0,0,0,0};
        gemm_2x8(sh_w, h0p, h1p, col0, f0a, f1a);

        // consume f: c_aggr += sigmoid(f_pre + b_f + f_input) * nc
        {
            float fp0[8], fp1[8];
            unpack8(f0a, fp0);
            unpack8(f1a, fp1);
            float cv0[8], cv1[8];
#pragma unroll
            for (int j = 0; j < 8; j++) { cv0[j] = 0.f; cv1[j] = 0.f; }
            if (v0) {
                *(float4*)&cv0[0] = *(const float4*)(nc + ((size_t)n0 * DEG + d) * HH + col0);
                *(float4*)&cv0[4] = *(const float4*)(nc + ((size_t)n0 * DEG + d) * HH + col0 + 4);
            }
            if (v1) {
                *(float4*)&cv1[0] = *(const float4*)(nc + ((size_t)n1 * DEG + d) * HH + col0);
                *(float4*)&cv1[4] = *(const float4*)(nc + ((size_t)n1 * DEG + d) * HH + col0 + 4);
            }
#pragma unroll
            for (int j = 0; j < 8; j++) {
                float b = sh_bf[d * HH + col0 + j];
                float g0 = sigmoidf_(fp0[j] + b + sh_fi[ln0 * HH + col0 + j]);
                float g1 = sigmoidf_(fp1[j] + b + sh_fi[ln1 * HH + col0 + j]);
                cag0[j] += g0 * cv0[j];
                cag1[j] += g1 * cv1[j];
            }
        }

        // ---- iou chunks: accumulate h_d @ U_aggr[d][:, ch*128 : (ch+1)*128] ----
#define LOAD_W_IOU(CH)                                                                 \
        {                                                                              \
            _Pragma("unroll")                                                          \
            for (int i = 0; i < (HH * HH / 4) / THREADS; i++) {                        \
                int idx = tid + i * THREADS;                                           \
                int r = idx >> 5, c4 = idx & 31;                                       \
                ((float4*)sh_w)[idx] =                                                 \
                    *(const float4*)(Ua + ((size_t)d * HH + r) * (3 * HH) + (CH) * HH + c4 * 4); \
            }                                                                          \
        }

        __syncthreads(); LOAD_W_IOU(0); __syncthreads();
        gemm_2x8(sh_w, h0p, h1p, col0, ai0, ai1);
        __syncthreads(); LOAD_W_IOU(1); __syncthreads();
        gemm_2x8(sh_w, h0p, h1p, col0, ao0, ao1);
        __syncthreads(); LOAD_W_IOU(2); __syncthreads();
        gemm_2x8(sh_w, h0p, h1p, col0, au0, au1);
#undef LOAD_W_IOU
    }

    // ---- epilogue ----
    float vi0[8], vo0[8], vu0[8], vi1[8], vo1[8], vu1[8];
    unpack8(ai0, vi0); unpack8(ao0, vo0); unpack8(au0, vu0);
    unpack8(ai1, vi1); unpack8(ao1, vo1); unpack8(au1, vu1);

    if (v0) {
        float ii[8], oo[8], uu[8], hv[8], cvv[8];
        const float* base = iou_in + (size_t)n0 * (3 * HH);
        *(float4*)&ii[0] = *(const float4*)(base + col0);
        *(float4*)&ii[4] = *(const float4*)(base + col0 + 4);
        *(float4*)&oo[0] = *(const float4*)(base + HH + col0);
        *(float4*)&oo[4] = *(const float4*)(base + HH + col0 + 4);
        *(float4*)&uu[0] = *(const float4*)(base + 2 * HH + col0);
        *(float4*)&uu[4] = *(const float4*)(base + 2 * HH + col0 + 4);
#pragma unroll
        for (int j = 0; j < 8; j++) {
            int col = col0 + j;
            float i_ = vi0[j] + sh_ba[col] + ii[j];
            float o_ = vo0[j] + sh_ba[HH + col] + oo[j];
            float u_ = vu0[j] + sh_ba[2 * HH + col] + uu[j];
            float c  = sigmoidf_(i_) * tanhf(u_) + cag0[j];
            cvv[j]   = c;
            hv[j]    = sigmoidf_(o_) * tanhf(c);
        }
        *(float4*)(out + (size_t)n0 * HH + col0)     = *(float4*)&hv[0];
        *(float4*)(out + (size_t)n0 * HH + col0 + 4) = *(float4*)&hv[4];
        *(float4*)(out + (size_t)NN * HH + (size_t)n0 * HH + col0)     = *(float4*)&cvv[0];
        *(float4*)(out + (size_t)NN * HH + (size_t)n0 * HH + col0 + 4) = *(float4*)&cvv[4];
    }
    if (v1) {
        float ii[8], oo[8], uu[8], hv[8], cvv[8];
        const float* base = iou_in + (size_t)n1 * (3 * HH);
        *(float4*)&ii[0] = *(const float4*)(base + col0);
        *(float4*)&ii[4] = *(const float4*)(base + col0 + 4);
        *(float4*)&oo[0] = *(const float4*)(base + HH + col0);
        *(float4*)&oo[4] = *(const float4*)(base + HH + col0 + 4);
        *(float4*)&uu[0] = *(const float4*)(base + 2 * HH + col0);
        *(float4*)&uu[4] = *(const float4*)(base + 2 * HH + col0 + 4);
#pragma unroll
        for (int j = 0; j < 8; j++) {
            int col = col0 + j;
            float i_ = vi1[j] + sh_ba[col] + ii[j];
            float o_ = vo1[j] + sh_ba[HH + col] + oo[j];
            float u_ = vu1[j] + sh_ba[2 * HH + col] + uu[j];
            float c  = sigmoidf_(i_) * tanhf(u_) + cag1[j];
            cvv[j]   = c;
            hv[j]    = sigmoidf_(o_) * tanhf(c);
        }
        *(float4*)(out + (size_t)n1 * HH + col0)     = *(float4*)&hv[0];
        *(float4*)(out + (size_t)n1 * HH + col0 + 4) = *(float4*)&hv[4];
        *(float4*)(out + (size_t)NN * HH + (size_t)n1 * HH + col0)     = *(float4*)&cvv[0];
        *(float4*)(out + (size_t)NN * HH + (size_t)n1 * HH + col0 + 4) = *(float4*)&cvv[4];
    }
}

extern "C" void kernel_launch(void* const* d_in, const int* in_sizes, int n_in,
                              void* d_out, int out_size) {
    const float* nh     = (const float*)d_in[0];
    const float* ncv    = (const float*)d_in[1];
    const float* f_in   = (const float*)d_in[2];
    const float* iou_in = (const float*)d_in[3];
    const float* Uf     = (const float*)d_in[4];
    const float* bf     = (const float*)d_in[5];
    const float* Ua     = (const float*)d_in[6];
    const float* ba     = (const float*)d_in[7];
    float* out = (float*)d_out;

    const int smem_bytes = SMEM_FLOATS * sizeof(float);   // 136704 B
    cudaFuncSetAttribute(tree_lstm_kernel,
                         cudaFuncAttributeMaxDynamicSharedMemorySize, smem_bytes);

    const int grid = (NN + TM - 1) / TM;                  // 1563
    tree_lstm_kernel<<<grid, THREADS, smem_bytes>>>(nh, ncv, f_in, iou_in,
                                                    Uf, bf, Ua, ba, out);
}

// round 4
// speedup vs baseline: 3.4502x; 3.4502x over previous
#include <cuda_runtime.h>
#include <cuda_bf16.h>
#include <cstdint>

#define NN   100000
#define DEG  8
#define HH   128
#define KTOT 1024          // DEG*HH
#define NOUT 384           // 3*HH

// ---------------- device scratch (static allocs are legal) ----------------
__device__ float g_cag[(size_t)NN * HH];                       // 51.2 MB
__device__ __align__(16) __nv_bfloat16 g_w1hi[DEG * HH * HH];  // Uf^T hi  [d][n][k]
__device__ __align__(16) __nv_bfloat16 g_w1lo[DEG * HH * HH];
__device__ __align__(16) __nv_bfloat16 g_w2hi[NOUT * KTOT];    // Ua^T hi  [n'][k]
__device__ __align__(16) __nv_bfloat16 g_w2lo[NOUT * KTOT];

// ---------------- helpers ----------------
static __device__ __forceinline__ uint32_t smem_u32(const void* p) {
    uint32_t a;
    asm("{ .reg .u64 t; cvta.to.shared.u64 t, %1; cvt.u32.u64 %0, t; }" : "=r"(a) : "l"(p));
    return a;
}
static __device__ __forceinline__ void ldmx4(uint32_t r[4], uint32_t addr) {
    asm volatile("ldmatrix.sync.aligned.m8n8.x4.shared.b16 {%0,%1,%2,%3}, [%4];"
                 : "=r"(r[0]), "=r"(r[1]), "=r"(r[2]), "=r"(r[3]) : "r"(addr));
}
static __device__ __forceinline__ void mma16816(float c[4], const uint32_t a[4], const uint32_t b[2]) {
    asm volatile("mma.sync.aligned.m16n8k16.row.col.f32.bf16.bf16.f32 "
                 "{%0,%1,%2,%3},{%4,%5,%6,%7},{%8,%9},{%0,%1,%2,%3};"
                 : "+f"(c[0]), "+f"(c[1]), "+f"(c[2]), "+f"(c[3])
                 : "r"(a[0]), "r"(a[1]), "r"(a[2]), "r"(a[3]), "r"(b[0]), "r"(b[1]));
}
static __device__ __forceinline__ void cp16(uint32_t dst, const void* src) {
    asm volatile("cp.async.cg.shared.global [%0], [%1], 16;"
                 :: "r"(dst), "l"(__cvta_generic_to_global(src)) : "memory");
}
#define CP_COMMIT() asm volatile("cp.async.commit_group;" ::: "memory")
#define CP_WAIT0()  asm volatile("cp.async.wait_group 0;" ::: "memory")
#define CP_WAIT1()  asm volatile("cp.async.wait_group 1;" ::: "memory")

static __device__ __forceinline__ float sigm(float x) { return 1.f / (1.f + __expf(-x)); }
static __device__ __forceinline__ void split_bf16(float x, uint32_t& h, uint32_t& l) {
    __nv_bfloat16 hb = __float2bfloat16(x);
    __nv_bfloat16 lb = __float2bfloat16(x - __bfloat162float(hb));
    h = (uint32_t)__bfloat16_as_ushort(hb);
    l = (uint32_t)__bfloat16_as_ushort(lb);
}
// pack two f32 -> (hi u32, lo u32) bf16x2 (element0 in low half)
static __device__ __forceinline__ void pack2(float a, float b, uint32_t& ph, uint32_t& pl) {
    uint32_t ha, la, hb, lb;
    split_bf16(a, ha, la); split_bf16(b, hb, lb);
    ph = ha | (hb << 16);
    pl = la | (lb << 16);
}

// ---------------- prep: transpose + split weights ----------------
__global__ void prep_weights(const float* __restrict__ Uf, const float* __restrict__ Ua) {
    int t = blockIdx.x * blockDim.x + threadIdx.x;
    if (t < DEG * HH * HH) {                 // W1: [d][n][k] = Uf[d][k][n]
        int k = t & 127, n = (t >> 7) & 127, d = t >> 14;
        float v = Uf[((size_t)d * HH + k) * HH + n];
        uint32_t h, l; split_bf16(v, h, l);
        g_w1hi[t] = __ushort_as_bfloat16((unsigned short)h);
        g_w1lo[t] = __ushort_as_bfloat16((unsigned short)l);
        return;
    }
    int u = t - DEG * HH * HH;
    if (u < NOUT * KTOT) {                   // W2: [n'][k], n' = grp*24 + ch*8 + c8
        int k = u & 1023, np = u >> 10;
        int grp = np / 24, rem = np - grp * 24;
        int ch = rem >> 3, c8 = rem & 7;
        int col = grp * 8 + c8;
        int d = k >> 7, h = k & 127;
        float v = Ua[((size_t)d * HH + h) * NOUT + ch * HH + col];
        uint32_t hh_, ll_; split_bf16(v, hh_, ll_);
        g_w2hi[u] = __ushort_as_bfloat16((unsigned short)hh_);
        g_w2lo[u] = __ushort_as_bfloat16((unsigned short)ll_);
    }
}

// =====================================================================
// Kernel 1: c_aggr.  CTA: M=128 nodes, 256 thr (8 warps, 2m x 4n), warp tile 64x32.
// smem rows padded: 128 bf16 = 256B rows, stride 272B.
// =====================================================================
#define K1_AST 272
#define K1_A_HI 0
#define K1_A_LO 34816
#define K1_B0   69632          // each B buffer = hi(34816)+lo(34816)
#define K1_B1   139264
#define K1_SMEM 208896

static __device__ __forceinline__ void k1_load_b(uint32_t sb, uint32_t bufoff,
                                                 int d, int tid) {
    // copy 32KB hi + 32KB lo into padded rows (2048 granules each)
    const __nv_bfloat16* srch = g_w1hi + (size_t)d * HH * HH;
    const __nv_bfloat16* srcl = g_w1lo + (size_t)d * HH * HH;
#pragma unroll
    for (int i = 0; i < 8; i++) {
        int idx = tid + i * 256;           // 0..2047
        int r = idx >> 4, g = idx & 15;
        uint32_t doff = bufoff + r * K1_AST + g * 16;
        cp16(sb + doff,           (const char*)srch + idx * 16);
        cp16(sb + doff + 34816,   (const char*)srcl + idx * 16);
    }
}

__global__ __launch_bounds__(256, 1)
void k1_caggr(const float* __restrict__ nh, const float* __restrict__ ncv,
              const float* __restrict__ f_in, const float* __restrict__ bf) {
    extern __shared__ unsigned char smb[];
    const uint32_t sb = smem_u32(smb);
    const int tid = threadIdx.x, wid = tid >> 5, l = tid & 31;
    const int wm = wid & 1, wn = wid >> 1;
    const int nb = blockIdx.x * 128;

    // per-lane ldmatrix offsets (within a tile section)
    uint32_t aoff[4], boff[2];
#pragma unroll
    for (int fm = 0; fm < 4; fm++)
        aoff[fm] = (uint32_t)(wm * 64 + fm * 16 + (l & 15)) * K1_AST + (uint32_t)(l >> 4) * 16;
#pragma unroll
    for (int p = 0; p < 2; p++)
        boff[p] = (uint32_t)(wn * 32 + p * 16 + (l & 7) + ((l >> 4) ? 8 : 0)) * K1_AST
                + (uint32_t)((l >> 3) & 1) * 16;

    float cag[4][4][4];
#pragma unroll
    for (int a = 0; a < 4; a++)
#pragma unroll
        for (int b = 0; b < 4; b++)
#pragma unroll
            for (int c = 0; c < 4; c++) cag[a][b][c] = 0.f;

    k1_load_b(sb, K1_B0, 0, tid);
    CP_COMMIT();

    const int arow = tid & 127, ahalf = tid >> 7;
    const int anode = nb + arow;

    for (int d = 0; d < DEG; d++) {
        if (d > 0) __syncthreads();   // prev compute done before A overwrite

        // ---- A: load f32, split, STS ----
        {
            const float* src = nh + ((size_t)anode * DEG + d) * HH + ahalf * 64;
            uint32_t abase = sb + K1_A_HI + arow * K1_AST + ahalf * 128;
#pragma unroll
            for (int j = 0; j < 8; j++) {
                float4 v0 = make_float4(0.f,0.f,0.f,0.f), v1 = v0;
                if (anode < NN) { v0 = *(const float4*)(src + j * 8); v1 = *(const float4*)(src + j * 8 + 4); }
                uint32_t h[4], lo[4];
                pack2(v0.x, v0.y, h[0], lo[0]); pack2(v0.z, v0.w, h[1], lo[1]);
                pack2(v1.x, v1.y, h[2], lo[2]); pack2(v1.z, v1.w, h[3], lo[3]);
                uint32_t dst = abase + j * 16;
                asm volatile("st.shared.v4.b32 [%0], {%1,%2,%3,%4};" :: "r"(dst), "r"(h[0]), "r"(h[1]), "r"(h[2]), "r"(h[3]) : "memory");
                asm volatile("st.shared.v4.b32 [%0], {%1,%2,%3,%4};" :: "r"(dst + (K1_A_LO - K1_A_HI)), "r"(lo[0]), "r"(lo[1]), "r"(lo[2]), "r"(lo[3]) : "memory");
            }
        }
        if (d < 7) { k1_load_b(sb, (d & 1) ? K1_B0 : K1_B1, d + 1, tid); CP_COMMIT(); CP_WAIT1(); }
        else       { CP_WAIT0(); }
        __syncthreads();

        const uint32_t bbase = sb + ((d & 1) ? K1_B1 : K1_B0);

        // ---- GEMM: f_pre = A @ B, 3-term split ----
        float facc[4][4][4];
#pragma unroll
        for (int a = 0; a < 4; a++)
#pragma unroll
            for (int b = 0; b < 4; b++)
#pragma unroll
                for (int c = 0; c < 4; c++) facc[a][b][c] = 0.f;

#pragma unroll
        for (int ks = 0; ks < 8; ks++) {
            uint32_t ah[4][4], al[4][4], bh[4][2], bl[4][2];
#pragma unroll
            for (int fm = 0; fm < 4; fm++) {
                ldmx4(ah[fm], sb + K1_A_HI + aoff[fm] + ks * 32);
                ldmx4(al[fm], sb + K1_A_LO + aoff[fm] + ks * 32);
            }
#pragma unroll
            for (int p = 0; p < 2; p++) {
                uint32_t r[4];
                ldmx4(r, bbase + boff[p] + ks * 32);
                bh[p*2][0]=r[0]; bh[p*2][1]=r[1]; bh[p*2+1][0]=r[2]; bh[p*2+1][1]=r[3];
                ldmx4(r, bbase + 34816 + boff[p] + ks * 32);
                bl[p*2][0]=r[0]; bl[p*2][1]=r[1]; bl[p*2+1][0]=r[2]; bl[p*2+1][1]=r[3];
            }
#pragma unroll
            for (int fm = 0; fm < 4; fm++)
#pragma unroll
                for (int fn = 0; fn < 4; fn++) {
                    mma16816(facc[fm][fn], ah[fm], bh[fn]);
                    mma16816(facc[fm][fn], ah[fm], bl[fn]);
                    mma16816(facc[fm][fn], al[fm], bh[fn]);
                }
        }

        // ---- epilogue: cag += sigmoid(f_pre + b_f + f_input) * nc ----
#pragma unroll
        for (int fm = 0; fm < 4; fm++)
#pragma unroll
            for (int rh = 0; rh < 2; rh++) {
                int node = nb + wm * 64 + fm * 16 + (l >> 2) + rh * 8;
                if (node >= NN) continue;
#pragma unroll
                for (int fn = 0; fn < 4; fn++) {
                    int col = wn * 32 + fn * 8 + (l & 3) * 2;
                    float2 fi = *(const float2*)(f_in + (size_t)node * HH + col);
                    float2 nc2 = *(const float2*)(ncv + ((size_t)node * DEG + d) * HH + col);
                    float2 bf2 = *(const float2*)(bf + d * HH + col);
                    cag[fm][fn][rh*2+0] += sigm(facc[fm][fn][rh*2+0] + bf2.x + fi.x) * nc2.x;
                    cag[fm][fn][rh*2+1] += sigm(facc[fm][fn][rh*2+1] + bf2.y + fi.y) * nc2.y;
                }
            }
    }

    // ---- store c_aggr ----
#pragma unroll
    for (int fm = 0; fm < 4; fm++)
#pragma unroll
        for (int rh = 0; rh < 2; rh++) {
            int node = nb + wm * 64 + fm * 16 + (l >> 2) + rh * 8;
            if (node >= NN) continue;
#pragma unroll
            for (int fn = 0; fn < 4; fn++) {
                int col = wn * 32 + fn * 8 + (l & 3) * 2;
                *(float2*)(g_cag + (size_t)node * HH + col) =
                    make_float2(cag[fm][fn][rh*2+0], cag[fm][fn][rh*2+1]);
            }
        }
}

// =====================================================================
// Kernel 2: iou GEMM (M=100000, N=384, K=1024) + epilogue.
// CTA: M=64, 256 thr (8 warps, 2m x 4n), warp tile 32x96. kc=32, double-buffered.
// smem rows: B/A = 64B data + 16 pad = 80B stride.
// =====================================================================
#define K2_BST 80
#define K2_BUF 71680           // Bhi 30720 | Blo 30720 | Ahi 5120 | Alo 5120
#define K2_BHI 0
#define K2_BLO 30720
#define K2_AHI 61440
#define K2_ALO 66560
#define K2_SMEM (2 * K2_BUF)   // 143360

__global__ __launch_bounds__(256, 1)
void k2_iou(const float* __restrict__ nh, const float* __restrict__ iou_in,
            const float* __restrict__ ba, float* __restrict__ out) {
    extern __shared__ unsigned char smb[];
    const uint32_t sb = smem_u32(smb);
    const int tid = threadIdx.x, wid = tid >> 5, l = tid & 31;
    const int wm = wid & 1, wn = wid >> 1;
    const int nb = blockIdx.x * 64;

    uint32_t aoff[2], boff[6];
#pragma unroll
    for (int fm = 0; fm < 2; fm++)
        aoff[fm] = (uint32_t)(wm * 32 + fm * 16 + (l & 15)) * K2_BST + (uint32_t)(l >> 4) * 16;
#pragma unroll
    for (int p = 0; p < 6; p++)
        boff[p] = (uint32_t)(wn * 96 + p * 16 + (l & 7) + ((l >> 4) ? 8 : 0)) * K2_BST
                + (uint32_t)((l >> 3) & 1) * 16;

    float acc[2][12][4];
#pragma unroll
    for (int a = 0; a < 2; a++)
#pragma unroll
        for (int b = 0; b < 12; b++)
#pragma unroll
            for (int c = 0; c < 4; c++) acc[a][b][c] = 0.f;

    const int arow = tid & 63, aq = tid >> 6;       // A: row, 8-float quad
    const int anode = nb + arow;
    const float* asrc = nh + (size_t)anode * KTOT + aq * 8;

    // ---- prologue: chunk 0 ----
    {
        float4 v0 = make_float4(0,0,0,0), v1 = v0;
        if (anode < NN) { v0 = *(const float4*)(asrc); v1 = *(const float4*)(asrc + 4); }
        uint32_t h[4], lo[4];
        pack2(v0.x, v0.y, h[0], lo[0]); pack2(v0.z, v0.w, h[1], lo[1]);
        pack2(v1.x, v1.y, h[2], lo[2]); pack2(v1.z, v1.w, h[3], lo[3]);
        uint32_t ad = sb + K2_AHI + arow * K2_BST + aq * 16;
        asm volatile("st.shared.v4.b32 [%0], {%1,%2,%3,%4};" :: "r"(ad), "r"(h[0]), "r"(h[1]), "r"(h[2]), "r"(h[3]) : "memory");
        asm volatile("st.shared.v4.b32 [%0], {%1,%2,%3,%4};" :: "r"(ad + (K2_ALO - K2_AHI)), "r"(lo[0]), "r"(lo[1]), "r"(lo[2]), "r"(lo[3]) : "memory");
#pragma unroll
        for (int i = 0; i < 6; i++) {
            int idx = tid + i * 256;               // 0..1535
            int r = idx >> 2, g = idx & 3;
            uint32_t doff = sb + r * K2_BST + g * 16;
            cp16(doff + K2_BHI, (const char*)(g_w2hi + (size_t)r * KTOT) + g * 16);
            cp16(doff + K2_BLO, (const char*)(g_w2lo + (size_t)r * KTOT) + g * 16);
        }
        CP_COMMIT(); CP_WAIT0();
    }
    __syncthreads();

    for (int kc = 0; kc < 32; kc++) {
        const uint32_t cur = sb + (kc & 1) * K2_BUF;
        const uint32_t nxt = sb + ((kc + 1) & 1) * K2_BUF;

        // issue next chunk's loads
        float4 v0, v1;
        bool have_next = (kc < 31);
        if (have_next) {
            v0 = make_float4(0,0,0,0); v1 = v0;
            if (anode < NN) {
                v0 = *(const float4*)(asrc + (kc + 1) * 32);
                v1 = *(const float4*)(asrc + (kc + 1) * 32 + 4);
            }
#pragma unroll
            for (int i = 0; i < 6; i++) {
                int idx = tid + i * 256;
                int r = idx >> 2, g = idx & 3;
                uint32_t doff = nxt + r * K2_BST + g * 16;
                const char* sh = (const char*)(g_w2hi + (size_t)r * KTOT) + (kc + 1) * 64 + g * 16;
                const char* sl = (const char*)(g_w2lo + (size_t)r * KTOT) + (kc + 1) * 64 + g * 16;
                cp16(doff + K2_BHI, sh);
                cp16(doff + K2_BLO, sl);
            }
            CP_COMMIT();
        }

        // ---- compute chunk kc (2 ksteps) ----
#pragma unroll
        for (int ks = 0; ks < 2; ks++) {
            uint32_t ah[2][4], al[2][4], bh[12][2], bl[12][2];
#pragma unroll
            for (int fm = 0; fm < 2; fm++) {
                ldmx4(ah[fm], cur + K2_AHI + aoff[fm] + ks * 32);
                ldmx4(al[fm], cur + K2_ALO + aoff[fm] + ks * 32);
            }
#pragma unroll
            for (int p = 0; p < 6; p++) {
                uint32_t r[4];
                ldmx4(r, cur + K2_BHI + boff[p] + ks * 32);
                bh[p*2][0]=r[0]; bh[p*2][1]=r[1]; bh[p*2+1][0]=r[2]; bh[p*2+1][1]=r[3];
                ldmx4(r, cur + K2_BLO + boff[p] + ks * 32);
                bl[p*2][0]=r[0]; bl[p*2][1]=r[1]; bl[p*2+1][0]=r[2]; bl[p*2+1][1]=r[3];
            }
#pragma unroll
            for (int fm = 0; fm < 2; fm++)
#pragma unroll
                for (int fn = 0; fn < 12; fn++) {
                    mma16816(acc[fm][fn], ah[fm], bh[fn]);
                    mma16816(acc[fm][fn], ah[fm], bl[fn]);
                    mma16816(acc[fm][fn], al[fm], bh[fn]);
                }
        }

        if (have_next) {
            uint32_t h[4], lo[4];
            pack2(v0.x, v0.y, h[0], lo[0]); pack2(v0.z, v0.w, h[1], lo[1]);
            pack2(v1.x, v1.y, h[2], lo[2]); pack2(v1.z, v1.w, h[3], lo[3]);
            uint32_t ad = nxt + K2_AHI + arow * K2_BST + aq * 16;
            asm volatile("st.shared.v4.b32 [%0], {%1,%2,%3,%4};" :: "r"(ad), "r"(h[0]), "r"(h[1]), "r"(h[2]), "r"(h[3]) : "memory");
            asm volatile("st.shared.v4.b32 [%0], {%1,%2,%3,%4};" :: "r"(ad + (K2_ALO - K2_AHI)), "r"(lo[0]), "r"(lo[1]), "r"(lo[2]), "r"(lo[3]) : "memory");
            CP_WAIT0();
        }
        __syncthreads();
    }

    // ---- epilogue: combine i,o,u + iou_in + ba + c_aggr -> h, c ----
#pragma unroll
    for (int fm = 0; fm < 2; fm++)
#pragma unroll
        for (int rh = 0; rh < 2; rh++) {
            int node = nb + wm * 32 + fm * 16 + (l >> 2) + rh * 8;
            if (node >= NN) continue;
            const float* ib = iou_in + (size_t)node * NOUT;
#pragma unroll
            for (int g = 0; g < 4; g++) {
                int col = (wn * 4 + g) * 8 + (l & 3) * 2;
                float2 ii = *(const float2*)(ib + col);
                float2 oo = *(const float2*)(ib + HH + col);
                float2 uu = *(const float2*)(ib + 2 * HH + col);
                float2 bi = *(const float2*)(ba + col);
                float2 bo = *(const float2*)(ba + HH + col);
                float2 bu = *(const float2*)(ba + 2 * HH + col);
                float2 cg = *(const float2*)(g_cag + (size_t)node * HH + col);
                float hv[2], cv[2];
#pragma unroll
                for (int e = 0; e < 2; e++) {
                    float iv = acc[fm][g*3+0][rh*2+e] + ((e) ? ii.y + bi.y : ii.x + bi.x);
                    float ov = acc[fm][g*3+1][rh*2+e] + ((e) ? oo.y + bo.y : oo.x + bo.x);
                    float uv = acc[fm][g*3+2][rh*2+e] + ((e) ? uu.y + bu.y : uu.x + bu.x);
                    float c  = sigm(iv) * tanhf(uv) + ((e) ? cg.y : cg.x);
                    cv[e] = c;
                    hv[e] = sigm(ov) * tanhf(c);
                }
                *(float2*)(out + (size_t)node * HH + col) = make_float2(hv[0], hv[1]);
                *(float2*)(out + (size_t)NN * HH + (size_t)node * HH + col) = make_float2(cv[0], cv[1]);
            }
        }
}

// ---------------- launch ----------------
extern "C" void kernel_launch(void* const* d_in, const int* in_sizes, int n_in,
                              void* d_out, int out_size) {
    const float* nh     = (const float*)d_in[0];
    const float* ncv    = (const float*)d_in[1];
    const float* f_in   = (const float*)d_in[2];
    const float* iou_in = (const float*)d_in[3];
    const float* Uf     = (const float*)d_in[4];
    const float* bf     = (const float*)d_in[5];
    const float* Ua     = (const float*)d_in[6];
    const float* ba     = (const float*)d_in[7];
    float* out = (float*)d_out;

    prep_weights<<<2048, 256>>>(Uf, Ua);

    cudaFuncSetAttribute(k1_caggr, cudaFuncAttributeMaxDynamicSharedMemorySize, K1_SMEM);
    cudaFuncSetAttribute(k2_iou,   cudaFuncAttributeMaxDynamicSharedMemorySize, K2_SMEM);

    k1_caggr<<<(NN + 127) / 128, 256, K1_SMEM>>>(nh, ncv, f_in, bf);
    k2_iou<<<(NN + 63) / 64, 256, K2_SMEM>>>(nh, iou_in, ba, out);
}